// round 13
// baseline (speedup 1.0000x reference)
#include <cuda_runtime.h>
#include <cuda_bf16.h>
#include <stdint.h>

#define B_DIM 128
#define C_DIM 2048
#define HW 196
#define NC 8
#define NM 4
#define NOUT 24                    // 8 A + 8 Z + 8 Y
#define PART_N (B_DIM * HW)        // 25088
#define SLABS 8
#define CSLAB (C_DIM / SLABS)      // 256
#define NKC (CSLAB / 16)           // 16 k-chunks per slab
#define WSTR 264                   // padded k-stride for W smem (bank-clean)

// ---- scratch (__device__ globals; no allocation allowed) ----
__device__ float g_part[SLABS * NOUT * PART_N];   // 19.3 MB

// ---------------- mma helper: m16n8k16 bf16 x bf16 -> fp32 ----------------
__device__ __forceinline__ void mma_bf16(float* d, const uint32_t* a,
                                         const uint32_t* bb) {
    asm volatile(
        "mma.sync.aligned.m16n8k16.row.col.f32.bf16.bf16.f32 "
        "{%0,%1,%2,%3}, {%4,%5,%6,%7}, {%8,%9}, {%0,%1,%2,%3};"
        : "+f"(d[0]), "+f"(d[1]), "+f"(d[2]), "+f"(d[3])
        : "r"(a[0]), "r"(a[1]), "r"(a[2]), "r"(a[3]),
          "r"(bb[0]), "r"(bb[1]));
}

// pack two fp32 into bf16x2: low half = x0, high half = x1
__device__ __forceinline__ uint32_t pack_bf16x2(float lo, float hi) {
    uint32_t r;
    asm("cvt.rn.bf16x2.f32 %0, %1, %2;" : "=r"(r) : "f"(hi), "f"(lo));
    return r;
}

// split (x0, x1) into hi bf16x2 + residual-lo bf16x2 (registers only)
__device__ __forceinline__ void split2(float x0, float x1,
                                       uint32_t& h, uint32_t& l) {
    h = pack_bf16x2(x0, x1);
    float h0 = __uint_as_float(h << 16);
    float h1 = __uint_as_float(h & 0xffff0000u);
    l = pack_bf16x2(x0 - h0, x1 - h1);
}

__device__ __forceinline__ void split_w(float v, __nv_bfloat16& h,
                                        __nv_bfloat16& l) {
    h = __float2bfloat16_rn(v);
    l = __float2bfloat16_rn(v - __bfloat162float(h));
}

// A-fragment gmem load for tile mt at chunk kc (verified round-12 layout)
__device__ __forceinline__ void load_tile(const float* xb, int kc, int tig,
                                          int mt, int gid, float* f) {
    const float* r0 = xb + (size_t)(kc * 16 + 2 * tig) * HW;
    const int p0 = mt * 16 + gid;
    const int p1 = p0 + 8;
    if (mt < 12) {                 // full tiles: unguarded
        f[0] = r0[p0];            f[1] = r0[HW + p0];
        f[2] = r0[p1];            f[3] = r0[HW + p1];
        f[4] = r0[8 * HW + p0];   f[5] = r0[9 * HW + p0];
        f[6] = r0[8 * HW + p1];   f[7] = r0[9 * HW + p1];
    } else {                       // tile 12: px 192..207, guard >= 196
        const bool g = (p0 < HW);
        f[0] = g ? r0[p0] : 0.f;
        f[1] = g ? r0[HW + p0] : 0.f;
        f[4] = g ? r0[8 * HW + p0] : 0.f;
        f[5] = g ? r0[9 * HW + p0] : 0.f;
        f[2] = 0.f; f[3] = 0.f; f[6] = 0.f; f[7] = 0.f;   // p1 >= 200
    }
}

// ============================================================================
// K1: tensor-core GEMM, one block per (batch, k-slab). 128 threads (4 warps).
// SOFTWARE-PIPELINED: A-loads for chunk kc+1 are issued before the
// split+mma compute of chunk kc (register double buffer fb[2][4][8]), so
// DRAM latency is covered by ~170 warp-instructions of independent work.
// Load / mma / writeback mappings identical to the verified round-12 kernel.
// ============================================================================
__global__ void __launch_bounds__(128) k1_mma(
    const float* __restrict__ x,
    const float* __restrict__ w_down,
    const float* __restrict__ w_cls) {
    __shared__ __nv_bfloat16 Wh[NOUT * WSTR];
    __shared__ __nv_bfloat16 Wl[NOUT * WSTR];

    const int b = blockIdx.x;
    const int slab = blockIdx.y;
    const int t = threadIdx.x;
    const int lane = t & 31, w = t >> 5;
    const int gid = lane >> 2;        // groupID  (0..7)
    const int tig = lane & 3;         // thread-in-group (0..3)

    // ---- stage W slab: fold + bf16 split (once) ----
    for (int i = t; i < NOUT * CSLAB; i += 128) {
        const int n = i >> 8;
        const int c = i & 255;
        const int cg = slab * CSLAB + c;
        float val;
        if (n < 8) {
            float s0 = w_down[(n * NM + 0) * C_DIM + cg];
            float s1 = w_down[(n * NM + 1) * C_DIM + cg];
            float s2 = w_down[(n * NM + 2) * C_DIM + cg];
            float s3 = w_down[(n * NM + 3) * C_DIM + cg];
            val = 0.25f * ((s0 + s1) + (s2 + s3));
        } else if (n < 16) {
            val = w_cls[(n - 8) * 2 * C_DIM + cg];
        } else {
            val = w_cls[(n - 16) * 2 * C_DIM + C_DIM + cg];
        }
        __nv_bfloat16 h, l;
        split_w(val, h, l);
        Wh[n * WSTR + c] = h;
        Wl[n * WSTR + c] = l;
    }
    __syncthreads();

    const int nmt = (w == 0) ? 4 : 3;   // warp w -> m-tiles {w, w+4, w+8 (,12)}
    float acc[4][3][4];
#pragma unroll
    for (int i = 0; i < 4; ++i)
#pragma unroll
        for (int nt = 0; nt < 3; ++nt)
#pragma unroll
            for (int r = 0; r < 4; ++r) acc[i][nt][r] = 0.f;

    const float* xb = x + ((size_t)b * C_DIM + slab * CSLAB) * HW;

    // register double buffer for A values
    float fb[2][4][8];
#pragma unroll
    for (int i = 0; i < 4; ++i)
        if (i < nmt) load_tile(xb, 0, tig, w + 4 * i, gid, fb[0][i]);

#pragma unroll 1
    for (int kc = 0; kc < NKC; ++kc) {
        const int cur = kc & 1, nxt = cur ^ 1;

        // ---- prefetch next chunk's A values (independent of compute) ----
        if (kc + 1 < NKC) {
#pragma unroll
            for (int i = 0; i < 4; ++i)
                if (i < nmt)
                    load_tile(xb, kc + 1, tig, w + 4 * i, gid, fb[nxt][i]);
        }

        // ---- B fragments for this chunk (3 n-tiles, hi+lo) ----
        uint32_t bh[3][2], bl[3][2];
        const int kb = kc * 16 + 2 * tig;
#pragma unroll
        for (int nt = 0; nt < 3; ++nt) {
            const int n = nt * 8 + gid;
            bh[nt][0] = *(const uint32_t*)&Wh[n * WSTR + kb];
            bh[nt][1] = *(const uint32_t*)&Wh[n * WSTR + kb + 8];
            bl[nt][0] = *(const uint32_t*)&Wl[n * WSTR + kb];
            bl[nt][1] = *(const uint32_t*)&Wl[n * WSTR + kb + 8];
        }

        // ---- split + mma on current (already resident) values ----
#pragma unroll
        for (int i = 0; i < 4; ++i) {
            if (i >= nmt) break;
            const float* f = fb[cur][i];
            uint32_t ah[4], al[4];
            split2(f[0], f[1], ah[0], al[0]);
            split2(f[2], f[3], ah[1], al[1]);
            split2(f[4], f[5], ah[2], al[2]);
            split2(f[6], f[7], ah[3], al[3]);
#pragma unroll
            for (int nt = 0; nt < 3; ++nt) {
                mma_bf16(acc[i][nt], ah, bh[nt]);   // xh*wh
                mma_bf16(acc[i][nt], ah, bl[nt]);   // xh*wl
                mma_bf16(acc[i][nt], al, bh[nt]);   // xl*wh
            }
        }
    }

    // ---- writeback (verified round-12 mapping) ----
#pragma unroll
    for (int i = 0; i < 4; ++i) {
        if (i >= nmt) break;
        const int mt = w + 4 * i;
        const int px0 = mt * 16 + gid;
        const int px1 = px0 + 8;
#pragma unroll
        for (int nt = 0; nt < 3; ++nt) {
            const int o = nt * 8 + 2 * tig;
            float* base = g_part + ((size_t)slab * NOUT + o) * PART_N
                        + (size_t)b * HW;
            if (px0 < HW) {
                base[px0] = acc[i][nt][0];
                base[PART_N + px0] = acc[i][nt][1];
            }
            if (px1 < HW) {
                base[px1] = acc[i][nt][2];
                base[PART_N + px1] = acc[i][nt][3];
            }
        }
    }
}

// ============================================================================
// K2a: m_c + v.  grid (8, 128) x 224 threads.
// ============================================================================
__global__ void __launch_bounds__(224) k2a(
    const float* __restrict__ b_down,
    float* __restrict__ out_v,
    float* __restrict__ out_mc) {
    __shared__ float wpart[7];
    const int k = blockIdx.x;
    const int b = blockIdx.y;
    const int t = threadIdx.x;
    const int g0 = b * HW;

    float mc = 0.f;
    if (t < HW) {
        float a[SLABS];
#pragma unroll
        for (int s = 0; s < SLABS; ++s)
            a[s] = g_part[((size_t)s * NOUT + k) * PART_N + g0 + t];
        float sum = ((a[0] + a[1]) + (a[2] + a[3])) +
                    ((a[4] + a[5]) + (a[6] + a[7]));
        float beff = 0.25f * ((b_down[4 * k] + b_down[4 * k + 1]) +
                              (b_down[4 * k + 2] + b_down[4 * k + 3]));
        mc = sum + beff;
        out_mc[((size_t)b * NC + k) * HW + t] = mc;
    }
    float s = mc;
#pragma unroll
    for (int o = 16; o; o >>= 1) s += __shfl_down_sync(0xffffffffu, s, o);
    const int lane = t & 31, warp = t >> 5;
    if (lane == 0) wpart[warp] = s;
    __syncthreads();
    if (t == 0) {
        float tot = 0.f;
#pragma unroll
        for (int w = 0; w < 7; ++w) tot += wpart[w];
        out_v[b * NC + k] = tot * (1.0f / (float)HW);
    }
}

// ============================================================================
// K2b: m[b,p] = (1/NC) sum_k v[b,k]*m_c[b,k,p].  grid 128 x 224.
// ============================================================================
__global__ void __launch_bounds__(224) k2b(
    const float* __restrict__ v_in,
    const float* __restrict__ mc_in,
    float* __restrict__ out_m) {
    __shared__ float vsh[NC];
    const int b = blockIdx.x;
    const int t = threadIdx.x;
    if (t < NC) vsh[t] = v_in[b * NC + t];
    __syncthreads();
    if (t < HW) {
        float a[NC];
#pragma unroll
        for (int k = 0; k < NC; ++k)
            a[k] = mc_in[((size_t)b * NC + k) * HW + t];
        float m = 0.f;
#pragma unroll
        for (int k = 0; k < NC; ++k) m = fmaf(vsh[k], a[k], m);
        out_m[b * HW + t] = m * (1.0f / (float)NC);
    }
}

// ============================================================================
// K2c: output[b,k] = (1/HW) sum_p (Z[k,p] + m[p]*Y[k,p]) + b_cls[k].
// grid (8, 128) x 224 threads.
// ============================================================================
__global__ void __launch_bounds__(224) k2c(
    const float* __restrict__ m_in,
    const float* __restrict__ b_cls,
    float* __restrict__ out_output) {
    __shared__ float wpart[7];
    const int k = blockIdx.x;
    const int b = blockIdx.y;
    const int t = threadIdx.x;
    const int g0 = b * HW;

    float po = 0.f;
    if (t < HW) {
        float z[SLABS], y[SLABS];
#pragma unroll
        for (int s = 0; s < SLABS; ++s)
            z[s] = g_part[((size_t)s * NOUT + 8 + k) * PART_N + g0 + t];
#pragma unroll
        for (int s = 0; s < SLABS; ++s)
            y[s] = g_part[((size_t)s * NOUT + 16 + k) * PART_N + g0 + t];
        float m = m_in[b * HW + t];
        float zs = ((z[0] + z[1]) + (z[2] + z[3])) +
                   ((z[4] + z[5]) + (z[6] + z[7]));
        float ys = ((y[0] + y[1]) + (y[2] + y[3])) +
                   ((y[4] + y[5]) + (y[6] + y[7]));
        po = fmaf(m, ys, zs);
    }
    float s = po;
#pragma unroll
    for (int o = 16; o; o >>= 1) s += __shfl_down_sync(0xffffffffu, s, o);
    const int lane = t & 31, warp = t >> 5;
    if (lane == 0) wpart[warp] = s;
    __syncthreads();
    if (t == 0) {
        float tot = 0.f;
#pragma unroll
        for (int w = 0; w < 7; ++w) tot += wpart[w];
        out_output[b * NC + k] = tot * (1.0f / (float)HW) + b_cls[k];
    }
}

// ============================================================================
// kernel_launch: 4 launches, graph-capturable, deterministic.
// Output layout: v[128,8]@0, output[128,8]@1024, m[128,196]@2048,
//                m_c[128,8,196]@27136.
// ============================================================================
extern "C" void kernel_launch(void* const* d_in, const int* in_sizes, int n_in,
                              void* d_out, int out_size) {
    const float* x      = (const float*)d_in[0];
    const float* w_down = (const float*)d_in[1];
    const float* b_down = (const float*)d_in[2];
    const float* w_cls  = (const float*)d_in[3];
    const float* b_cls  = (const float*)d_in[4];

    float* out        = (float*)d_out;
    float* out_v      = out;
    float* out_output = out + 1024;
    float* out_m      = out + 2048;
    float* out_mc     = out + 27136;

    k1_mma<<<dim3(B_DIM, SLABS), 128>>>(x, w_down, w_cls);
    k2a<<<dim3(NC, B_DIM), 224>>>(b_down, out_v, out_mc);
    k2b<<<B_DIM, 224>>>(out_v, out_mc, out_m);
    k2c<<<dim3(NC, B_DIM), 224>>>(out_m, b_cls, out_output);
}

// round 15
// speedup vs baseline: 1.6600x; 1.6600x over previous
#include <cuda_runtime.h>
#include <stdint.h>

#define B_DIM 128
#define C_DIM 2048
#define HW 196
#define NC 8
#define NM 4
#define PART_N (B_DIM * HW)        // 25088
#define SLABS 8
#define CSLAB (C_DIM / SLABS)      // 256
#define PXT 4                      // pixels per thread
#define K1_THREADS 128
#define PXB (K1_THREADS * PXT)     // 512 pixels per block
#define NBX (PART_N / PXB)         // 49 pixel-blocks
#define NROW 16                    // per-pixel rows: 8 A + 8 Y

// ---- scratch (__device__ globals; no allocation allowed) ----
__device__ float g_part[SLABS * NROW * PART_N];      // A+Y slab partials, 12.8 MB
__device__ float g_zpart[SLABS * NBX * 4 * NC];      // Z partials per (slab,bx,seg,k)

// ---------------- packed f32x2 helpers (verified rounds 2-10) --------------
__device__ __forceinline__ unsigned long long fma2(
    unsigned long long a, unsigned long long b, unsigned long long c) {
    unsigned long long d;
    asm("fma.rn.f32x2 %0, %1, %2, %3;" : "=l"(d) : "l"(a), "l"(b), "l"(c));
    return d;
}
__device__ __forceinline__ unsigned long long dup2(float v) {
    unsigned long long d;
    asm("mov.b64 %0, {%1, %2};" : "=l"(d) : "f"(v), "f"(v));
    return d;
}
__device__ __forceinline__ void unpack2(unsigned long long v, float& lo, float& hi) {
    asm("mov.b64 {%0, %1}, %2;" : "=f"(lo), "=f"(hi) : "l"(v));
}

// ============================================================================
// K1: single streaming pass over x. grid (49, 8), 128 threads.
// Thread owns 4 adjacent pixels (float4 LDG). Per channel:
//   A[k] += w_eff[k]*x  (16 FMA2: per-pixel, for m_c)
//   Y[k] += w_hi[k]*x   (16 FMA2: per-pixel, for sum_p m*Y)
//   zacc[k] += w_lo[k]*(sum of 4 px)  (3 FADD + 4 FMA2: Z is only ever
//                                      consumed as its pixel-sum)
// A/Y -> g_part[slab][row][g]; zacc reduced per (block, batch-seg) -> g_zpart.
// ============================================================================
__global__ void __launch_bounds__(K1_THREADS, 4) k1_main(
    const float* __restrict__ x,
    const float* __restrict__ w_down,
    const float* __restrict__ w_cls) {
    __shared__ float wsh[CSLAB * 24];     // 24 KB: [c][0..7 A | 8..15 Y | 16..23 Z]
    __shared__ float zsm[K1_THREADS][NC]; // 4 KB

    const int bx = blockIdx.x;
    const int slab = blockIdx.y;
    const int t = threadIdx.x;

    // ---- inline weight prep ----
#pragma unroll
    for (int cl = t; cl < CSLAB; cl += K1_THREADS) {
        const int cg = slab * CSLAB + cl;
        float* w = &wsh[cl * 24];
#pragma unroll
        for (int k = 0; k < NC; ++k) {
            float s0 = w_down[(k * NM + 0) * C_DIM + cg];
            float s1 = w_down[(k * NM + 1) * C_DIM + cg];
            float s2 = w_down[(k * NM + 2) * C_DIM + cg];
            float s3 = w_down[(k * NM + 3) * C_DIM + cg];
            w[k]      = 0.25f * ((s0 + s1) + (s2 + s3));          // A (w_eff)
            w[8 + k]  = w_cls[k * 2 * C_DIM + C_DIM + cg];        // Y (w_hi)
            w[16 + k] = w_cls[k * 2 * C_DIM + cg];                // Z (w_lo)
        }
    }
    __syncthreads();

    const int g0 = bx * PXB + PXT * t;   // 4 pixels, one batch (4 | 196)
    const int b = g0 / HW;
    const int p = g0 - b * HW;

    unsigned long long accA[16], accY[16], zacc[4];
#pragma unroll
    for (int j = 0; j < 16; ++j) { accA[j] = dup2(0.f); accY[j] = dup2(0.f); }
#pragma unroll
    for (int j = 0; j < 4; ++j) zacc[j] = dup2(0.f);

    const float* xp = x + ((size_t)b * C_DIM + slab * CSLAB) * HW + p;

#pragma unroll 1
    for (int c0 = 0; c0 < CSLAB; c0 += 4) {
        float4 xv[4];
#pragma unroll
        for (int u = 0; u < 4; ++u)
            xv[u] = *(const float4*)&xp[(c0 + u) * HW];
#pragma unroll
        for (int u = 0; u < 4; ++u) {
            const float4 v = xv[u];
            unsigned long long xx[PXT];
            xx[0] = dup2(v.x); xx[1] = dup2(v.y);
            xx[2] = dup2(v.z); xx[3] = dup2(v.w);
            const ulonglong2* w = (const ulonglong2*)&wsh[(c0 + u) * 24];
            ulonglong2 wa0 = w[0], wa1 = w[1];       // A pairs
            ulonglong2 wy0 = w[2], wy1 = w[3];       // Y pairs
            ulonglong2 wz0 = w[4], wz1 = w[5];       // Z pairs
#pragma unroll
            for (int px = 0; px < PXT; ++px) {
                accA[0 * PXT + px] = fma2(xx[px], wa0.x, accA[0 * PXT + px]);
                accA[1 * PXT + px] = fma2(xx[px], wa0.y, accA[1 * PXT + px]);
                accA[2 * PXT + px] = fma2(xx[px], wa1.x, accA[2 * PXT + px]);
                accA[3 * PXT + px] = fma2(xx[px], wa1.y, accA[3 * PXT + px]);
                accY[0 * PXT + px] = fma2(xx[px], wy0.x, accY[0 * PXT + px]);
                accY[1 * PXT + px] = fma2(xx[px], wy0.y, accY[1 * PXT + px]);
                accY[2 * PXT + px] = fma2(xx[px], wy1.x, accY[2 * PXT + px]);
                accY[3 * PXT + px] = fma2(xx[px], wy1.y, accY[3 * PXT + px]);
            }
            // Z folded to pixel-sum
            float sx = (v.x + v.y) + (v.z + v.w);
            unsigned long long sxx = dup2(sx);
            zacc[0] = fma2(sxx, wz0.x, zacc[0]);
            zacc[1] = fma2(sxx, wz0.y, zacc[1]);
            zacc[2] = fma2(sxx, wz1.x, zacc[2]);
            zacc[3] = fma2(sxx, wz1.y, zacc[3]);
        }
    }

    // ---- write A/Y per-pixel partials (verified round-10 float4 writeback) ----
    float* base = &g_part[(size_t)slab * NROW * PART_N + g0];
#pragma unroll
    for (int j = 0; j < 4; ++j) {
        float lo[PXT], hi[PXT];
#pragma unroll
        for (int px = 0; px < PXT; ++px) unpack2(accA[j * PXT + px], lo[px], hi[px]);
        *(float4*)&base[(2 * j) * PART_N]     = make_float4(lo[0], lo[1], lo[2], lo[3]);
        *(float4*)&base[(2 * j + 1) * PART_N] = make_float4(hi[0], hi[1], hi[2], hi[3]);
#pragma unroll
        for (int px = 0; px < PXT; ++px) unpack2(accY[j * PXT + px], lo[px], hi[px]);
        *(float4*)&base[(8 + 2 * j) * PART_N]     = make_float4(lo[0], lo[1], lo[2], lo[3]);
        *(float4*)&base[(8 + 2 * j + 1) * PART_N] = make_float4(hi[0], hi[1], hi[2], hi[3]);
    }

    // ---- Z: segmented block reduction by batch (deterministic) ----
#pragma unroll
    for (int j = 0; j < 4; ++j) {
        float lo, hi;
        unpack2(zacc[j], lo, hi);
        zsm[t][2 * j] = lo;
        zsm[t][2 * j + 1] = hi;
    }
    __syncthreads();
    if (t < 32) {
        const int seg = t >> 3, k = t & 7;
        const int btgt = (bx * PXB) / HW + seg;
        float s = 0.f;
#pragma unroll 1
        for (int u = 0; u < K1_THREADS; ++u) {
            const int bu = (bx * PXB + PXT * u) / HW;
            if (bu == btgt) s += zsm[u][k];
        }
        g_zpart[(((size_t)slab * NBX + bx) * 4 + seg) * NC + k] = s;
    }
}

// ============================================================================
// K2: fused per-batch epilogue. grid 128 x 224 threads.
//   m_c[k,p] = sum_s A_part + beff[k] -> out_mc
//   v[k] = mean_p m_c -> out_v
//   m[p] = (1/8) sum_k v[k] m_c[k,p] -> out_m
//   output[k] = (1/HW)(sum_p m[p]*Y[k,p] + Zsum[k]) + b_cls[k]
// ============================================================================
__global__ void __launch_bounds__(224) k2_epi(
    const float* __restrict__ b_down,
    const float* __restrict__ b_cls,
    float* __restrict__ out_v,
    float* __restrict__ out_output,
    float* __restrict__ out_m,
    float* __restrict__ out_mc) {
    __shared__ float red[NC * 200];
    __shared__ float vsh[NC];
    __shared__ float besh[NC];
    __shared__ float wpart[7][NC];

    const int b = blockIdx.x;
    const int t = threadIdx.x;
    const int g0 = b * HW;

    if (t < NC)
        besh[t] = 0.25f * ((b_down[4 * t] + b_down[4 * t + 1]) +
                           (b_down[4 * t + 2] + b_down[4 * t + 3]));
    __syncthreads();

    // m_c from 8 slab partials (rows 0..7), loads front-batched
    if (t < HW) {
#pragma unroll
        for (int k = 0; k < NC; ++k) {
            float a[SLABS];
#pragma unroll
            for (int s = 0; s < SLABS; ++s)
                a[s] = g_part[((size_t)s * NROW + k) * PART_N + g0 + t];
            float sum = ((a[0] + a[1]) + (a[2] + a[3])) +
                        ((a[4] + a[5]) + (a[6] + a[7]));
            float mc = sum + besh[k];
            red[k * 200 + t] = mc;
            out_mc[((size_t)b * NC + k) * HW + t] = mc;
        }
    }
    __syncthreads();

    if (t < NC) {
        float s = 0.f;
        for (int p = 0; p < HW; ++p) s += red[t * 200 + p];
        float vv = s * (1.0f / (float)HW);
        vsh[t] = vv;
        out_v[b * NC + t] = vv;
    }
    __syncthreads();

    float m = 0.f;
    if (t < HW) {
#pragma unroll
        for (int k = 0; k < NC; ++k) m = fmaf(vsh[k], red[k * 200 + t], m);
        m *= (1.0f / (float)NC);
        out_m[b * HW + t] = m;
    }

    // po[k] = m[p] * Y[k,p] (Y rows 8..15), per-thread then block-reduced
    float po[NC];
#pragma unroll
    for (int k = 0; k < NC; ++k) po[k] = 0.f;
    if (t < HW) {
#pragma unroll
        for (int k = 0; k < NC; ++k) {
            float y[SLABS];
#pragma unroll
            for (int s = 0; s < SLABS; ++s)
                y[s] = g_part[((size_t)s * NROW + 8 + k) * PART_N + g0 + t];
            float ys = ((y[0] + y[1]) + (y[2] + y[3])) +
                       ((y[4] + y[5]) + (y[6] + y[7]));
            po[k] = m * ys;
        }
    }
#pragma unroll
    for (int o = 16; o; o >>= 1) {
#pragma unroll
        for (int k = 0; k < NC; ++k)
            po[k] += __shfl_down_sync(0xffffffffu, po[k], o);
    }
    const int lane = t & 31, warp = t >> 5;
    if (lane == 0) {
#pragma unroll
        for (int k = 0; k < NC; ++k) wpart[warp][k] = po[k];
    }
    __syncthreads();

    if (t < NC) {
        const int k = t;
        float s = 0.f;
#pragma unroll
        for (int w = 0; w < 7; ++w) s += wpart[w][k];
        // Z contribution: batch b's pixels live in <=2 pixel-blocks
        const int bx_lo = (b * HW) / PXB;
        const int bx_hi = (b * HW + HW - 1) / PXB;
        float z = 0.f;
        for (int bxx = bx_lo; bxx <= bx_hi; ++bxx) {
            const int seg = b - (bxx * PXB) / HW;
#pragma unroll
            for (int sl = 0; sl < SLABS; ++sl)
                z += g_zpart[(((size_t)sl * NBX + bxx) * 4 + seg) * NC + k];
        }
        out_output[b * NC + k] = (s + z) * (1.0f / (float)HW) + b_cls[k];
    }
}

// ============================================================================
// kernel_launch: 2 launches, graph-capturable, deterministic.
// Output layout: v[128,8]@0, output[128,8]@1024, m[128,196]@2048,
//                m_c[128,8,196]@27136.
// ============================================================================
extern "C" void kernel_launch(void* const* d_in, const int* in_sizes, int n_in,
                              void* d_out, int out_size) {
    const float* x      = (const float*)d_in[0];
    const float* w_down = (const float*)d_in[1];
    const float* b_down = (const float*)d_in[2];
    const float* w_cls  = (const float*)d_in[3];
    const float* b_cls  = (const float*)d_in[4];

    float* out        = (float*)d_out;
    float* out_v      = out;
    float* out_output = out + 1024;
    float* out_m      = out + 2048;
    float* out_mc     = out + 27136;

    k1_main<<<dim3(NBX, SLABS), K1_THREADS>>>(x, w_down, w_cls);
    k2_epi<<<B_DIM, 224>>>(b_down, b_cls, out_v, out_output, out_m, out_mc);
}

// round 16
// speedup vs baseline: 1.7610x; 1.0608x over previous
#include <cuda_runtime.h>
#include <stdint.h>

#define B_DIM 128
#define C_DIM 2048
#define HW 196
#define NC 8
#define NM 4
#define PART_N (B_DIM * HW)        // 25088
#define SLABS 8
#define CSLAB (C_DIM / SLABS)      // 256
#define PXT 4                      // pixels per thread
#define K1_THREADS 128
#define PXB (K1_THREADS * PXT)     // 512 pixels per block
#define NBX (PART_N / PXB)         // 49 pixel-blocks
#define NROW 16                    // per-pixel rows: 8 A + 8 Y

// ---- scratch (__device__ globals; no allocation allowed) ----
__device__ float g_part[SLABS * NROW * PART_N];      // A+Y slab partials, 12.8 MB
__device__ float g_zpart[SLABS * NBX * 4 * NC];      // Z partials per (slab,bx,seg,k)

// ---------------- packed f32x2 helpers (verified rounds 2-15) --------------
__device__ __forceinline__ unsigned long long fma2(
    unsigned long long a, unsigned long long b, unsigned long long c) {
    unsigned long long d;
    asm("fma.rn.f32x2 %0, %1, %2, %3;" : "=l"(d) : "l"(a), "l"(b), "l"(c));
    return d;
}
__device__ __forceinline__ unsigned long long dup2(float v) {
    unsigned long long d;
    asm("mov.b64 %0, {%1, %2};" : "=l"(d) : "f"(v), "f"(v));
    return d;
}
__device__ __forceinline__ void unpack2(unsigned long long v, float& lo, float& hi) {
    asm("mov.b64 {%0, %1}, %2;" : "=f"(lo), "=f"(hi) : "l"(v));
}

// ============================================================================
// K1: single streaming pass over x (verified round-15 math). grid (49, 8).
// Thread owns 4 adjacent pixels (float4 LDG). Per channel:
//   A[k] += w_eff[k]*x ; Y[k] += w_hi[k]*x ; zacc[k] += w_lo[k]*(4-px sum).
// A/Y -> g_part[slab][row][g]; zacc -> segmented block reduce -> g_zpart.
// ============================================================================
__global__ void __launch_bounds__(K1_THREADS, 4) k1_main(
    const float* __restrict__ x,
    const float* __restrict__ w_down,
    const float* __restrict__ w_cls) {
    __shared__ float wsh[CSLAB * 24];     // [c][0..7 A | 8..15 Y | 16..23 Z]
    __shared__ float zsm[K1_THREADS][NC];

    const int bx = blockIdx.x;
    const int slab = blockIdx.y;
    const int t = threadIdx.x;

    // ---- inline weight prep ----
#pragma unroll
    for (int cl = t; cl < CSLAB; cl += K1_THREADS) {
        const int cg = slab * CSLAB + cl;
        float* w = &wsh[cl * 24];
#pragma unroll
        for (int k = 0; k < NC; ++k) {
            float s0 = w_down[(k * NM + 0) * C_DIM + cg];
            float s1 = w_down[(k * NM + 1) * C_DIM + cg];
            float s2 = w_down[(k * NM + 2) * C_DIM + cg];
            float s3 = w_down[(k * NM + 3) * C_DIM + cg];
            w[k]      = 0.25f * ((s0 + s1) + (s2 + s3));          // A (w_eff)
            w[8 + k]  = w_cls[k * 2 * C_DIM + C_DIM + cg];        // Y (w_hi)
            w[16 + k] = w_cls[k * 2 * C_DIM + cg];                // Z (w_lo)
        }
    }
    __syncthreads();

    const int g0 = bx * PXB + PXT * t;   // 4 pixels, one batch (4 | 196)
    const int b = g0 / HW;
    const int p = g0 - b * HW;

    unsigned long long accA[16], accY[16], zacc[4];
#pragma unroll
    for (int j = 0; j < 16; ++j) { accA[j] = dup2(0.f); accY[j] = dup2(0.f); }
#pragma unroll
    for (int j = 0; j < 4; ++j) zacc[j] = dup2(0.f);

    const float* xp = x + ((size_t)b * C_DIM + slab * CSLAB) * HW + p;

#pragma unroll 2
    for (int c0 = 0; c0 < CSLAB; c0 += 4) {
        float4 xv[4];
#pragma unroll
        for (int u = 0; u < 4; ++u)
            xv[u] = *(const float4*)&xp[(c0 + u) * HW];
#pragma unroll
        for (int u = 0; u < 4; ++u) {
            const float4 v = xv[u];
            unsigned long long xx[PXT];
            xx[0] = dup2(v.x); xx[1] = dup2(v.y);
            xx[2] = dup2(v.z); xx[3] = dup2(v.w);
            const ulonglong2* w = (const ulonglong2*)&wsh[(c0 + u) * 24];
            ulonglong2 wa0 = w[0], wa1 = w[1];       // A pairs
            ulonglong2 wy0 = w[2], wy1 = w[3];       // Y pairs
            ulonglong2 wz0 = w[4], wz1 = w[5];       // Z pairs
#pragma unroll
            for (int px = 0; px < PXT; ++px) {
                accA[0 * PXT + px] = fma2(xx[px], wa0.x, accA[0 * PXT + px]);
                accA[1 * PXT + px] = fma2(xx[px], wa0.y, accA[1 * PXT + px]);
                accA[2 * PXT + px] = fma2(xx[px], wa1.x, accA[2 * PXT + px]);
                accA[3 * PXT + px] = fma2(xx[px], wa1.y, accA[3 * PXT + px]);
                accY[0 * PXT + px] = fma2(xx[px], wy0.x, accY[0 * PXT + px]);
                accY[1 * PXT + px] = fma2(xx[px], wy0.y, accY[1 * PXT + px]);
                accY[2 * PXT + px] = fma2(xx[px], wy1.x, accY[2 * PXT + px]);
                accY[3 * PXT + px] = fma2(xx[px], wy1.y, accY[3 * PXT + px]);
            }
            float sx = (v.x + v.y) + (v.z + v.w);
            unsigned long long sxx = dup2(sx);
            zacc[0] = fma2(sxx, wz0.x, zacc[0]);
            zacc[1] = fma2(sxx, wz0.y, zacc[1]);
            zacc[2] = fma2(sxx, wz1.x, zacc[2]);
            zacc[3] = fma2(sxx, wz1.y, zacc[3]);
        }
    }

    // ---- write A/Y per-pixel partials (float4, verified) ----
    float* base = &g_part[(size_t)slab * NROW * PART_N + g0];
#pragma unroll
    for (int j = 0; j < 4; ++j) {
        float lo[PXT], hi[PXT];
#pragma unroll
        for (int px = 0; px < PXT; ++px) unpack2(accA[j * PXT + px], lo[px], hi[px]);
        *(float4*)&base[(2 * j) * PART_N]     = make_float4(lo[0], lo[1], lo[2], lo[3]);
        *(float4*)&base[(2 * j + 1) * PART_N] = make_float4(hi[0], hi[1], hi[2], hi[3]);
#pragma unroll
        for (int px = 0; px < PXT; ++px) unpack2(accY[j * PXT + px], lo[px], hi[px]);
        *(float4*)&base[(8 + 2 * j) * PART_N]     = make_float4(lo[0], lo[1], lo[2], lo[3]);
        *(float4*)&base[(8 + 2 * j + 1) * PART_N] = make_float4(hi[0], hi[1], hi[2], hi[3]);
    }

    // ---- Z: segmented block reduction by batch (verified) ----
#pragma unroll
    for (int j = 0; j < 4; ++j) {
        float lo, hi;
        unpack2(zacc[j], lo, hi);
        zsm[t][2 * j] = lo;
        zsm[t][2 * j + 1] = hi;
    }
    __syncthreads();
    if (t < 32) {
        const int seg = t >> 3, k = t & 7;
        const int btgt = (bx * PXB) / HW + seg;
        float s = 0.f;
#pragma unroll 1
        for (int u = 0; u < K1_THREADS; ++u) {
            const int bu = (bx * PXB + PXT * u) / HW;
            if (bu == btgt) s += zsm[u][k];
        }
        g_zpart[(((size_t)slab * NBX + bx) * 4 + seg) * NC + k] = s;
    }
}

// ============================================================================
// K2a: per (k, b): m_c[b,k,p] = sum_s A_part + beff[k] -> out_mc;
//      v[b,k] = mean_p m_c -> out_v.  grid (8, 128) x 224 (wide, occupancy).
// ============================================================================
__global__ void __launch_bounds__(224) k2a(
    const float* __restrict__ b_down,
    float* __restrict__ out_v,
    float* __restrict__ out_mc) {
    __shared__ float wpart[7];
    const int k = blockIdx.x, b = blockIdx.y, t = threadIdx.x;
    const int g0 = b * HW;

    float mc = 0.f;
    if (t < HW) {
        float a[SLABS];
#pragma unroll
        for (int s = 0; s < SLABS; ++s)
            a[s] = g_part[((size_t)s * NROW + k) * PART_N + g0 + t];
        float sum = ((a[0] + a[1]) + (a[2] + a[3])) +
                    ((a[4] + a[5]) + (a[6] + a[7]));
        float beff = 0.25f * ((b_down[4 * k] + b_down[4 * k + 1]) +
                              (b_down[4 * k + 2] + b_down[4 * k + 3]));
        mc = sum + beff;
        out_mc[((size_t)b * NC + k) * HW + t] = mc;
    }
    float s = mc;
#pragma unroll
    for (int o = 16; o; o >>= 1) s += __shfl_down_sync(0xffffffffu, s, o);
    const int lane = t & 31, warp = t >> 5;
    if (lane == 0) wpart[warp] = s;
    __syncthreads();
    if (t == 0) {
        float tot = 0.f;
#pragma unroll
        for (int w = 0; w < 7; ++w) tot += wpart[w];
        out_v[b * NC + k] = tot * (1.0f / (float)HW);
    }
}

// ============================================================================
// K2b: m[b,p] = (1/NC) sum_k v[b,k]*m_c[b,k,p].  grid 128 x 224.
// ============================================================================
__global__ void __launch_bounds__(224) k2b(
    const float* __restrict__ v_in,
    const float* __restrict__ mc_in,
    float* __restrict__ out_m) {
    __shared__ float vsh[NC];
    const int b = blockIdx.x, t = threadIdx.x;
    if (t < NC) vsh[t] = v_in[b * NC + t];
    __syncthreads();
    if (t < HW) {
        float a[NC];
#pragma unroll
        for (int k = 0; k < NC; ++k)
            a[k] = mc_in[((size_t)b * NC + k) * HW + t];
        float m = 0.f;
#pragma unroll
        for (int k = 0; k < NC; ++k) m = fmaf(vsh[k], a[k], m);
        out_m[b * HW + t] = m * (1.0f / (float)NC);
    }
}

// ============================================================================
// K2c: output[b,k] = (1/HW)(sum_p m[p]*Ysum[k,p] + Zsum[b,k]) + b_cls[k].
// grid (8, 128) x 224 threads; 8 Y loads + m front-batched.
// ============================================================================
__global__ void __launch_bounds__(224) k2c(
    const float* __restrict__ m_in,
    const float* __restrict__ b_cls,
    float* __restrict__ out_output) {
    __shared__ float wpart[7];
    const int k = blockIdx.x, b = blockIdx.y, t = threadIdx.x;
    const int g0 = b * HW;

    float po = 0.f;
    if (t < HW) {
        float y[SLABS];
#pragma unroll
        for (int s = 0; s < SLABS; ++s)
            y[s] = g_part[((size_t)s * NROW + 8 + k) * PART_N + g0 + t];
        float m = m_in[g0 + t];
        float ys = ((y[0] + y[1]) + (y[2] + y[3])) +
                   ((y[4] + y[5]) + (y[6] + y[7]));
        po = m * ys;
    }
#pragma unroll
    for (int o = 16; o; o >>= 1) po += __shfl_down_sync(0xffffffffu, po, o);
    const int lane = t & 31, warp = t >> 5;
    if (lane == 0) wpart[warp] = po;
    __syncthreads();
    if (t == 0) {
        float tot = 0.f;
#pragma unroll
        for (int w = 0; w < 7; ++w) tot += wpart[w];
        // Z contribution: batch b's pixels live in <=2 pixel-blocks
        const int bx_lo = (b * HW) / PXB;
        const int bx_hi = (b * HW + HW - 1) / PXB;
        float z = 0.f;
        for (int bxx = bx_lo; bxx <= bx_hi; ++bxx) {
            const int seg = b - (bxx * PXB) / HW;
#pragma unroll
            for (int sl = 0; sl < SLABS; ++sl)
                z += g_zpart[(((size_t)sl * NBX + bxx) * 4 + seg) * NC + k];
        }
        out_output[b * NC + k] = (tot + z) * (1.0f / (float)HW) + b_cls[k];
    }
}

// ============================================================================
// kernel_launch: 4 launches, graph-capturable, deterministic.
// Output layout: v[128,8]@0, output[128,8]@1024, m[128,196]@2048,
//                m_c[128,8,196]@27136.
// ============================================================================
extern "C" void kernel_launch(void* const* d_in, const int* in_sizes, int n_in,
                              void* d_out, int out_size) {
    const float* x      = (const float*)d_in[0];
    const float* w_down = (const float*)d_in[1];
    const float* b_down = (const float*)d_in[2];
    const float* w_cls  = (const float*)d_in[3];
    const float* b_cls  = (const float*)d_in[4];

    float* out        = (float*)d_out;
    float* out_v      = out;
    float* out_output = out + 1024;
    float* out_m      = out + 2048;
    float* out_mc     = out + 27136;

    k1_main<<<dim3(NBX, SLABS), K1_THREADS>>>(x, w_down, w_cls);
    k2a<<<dim3(NC, B_DIM), 224>>>(b_down, out_v, out_mc);
    k2b<<<B_DIM, 224>>>(out_v, out_mc, out_m);
    k2c<<<dim3(NC, B_DIM), 224>>>(out_m, b_cls, out_output);
}